// round 11
// baseline (speedup 1.0000x reference)
#include <cuda_runtime.h>

#define BB   16
#define HH   64
#define LL   16384
#define NN   32
#define DCC  128
#define TT   512
#define NCHK 32
#define NSEQ (BB*HH)
#define NTOT (BB*HH*LL)

typedef unsigned long long u64;

__device__ float  g_buf0[NTOT];
__device__ float  g_buf1[NTOT];
__device__ float2 g_wre [HH*NN/2];
__device__ float2 g_wim [HH*NN/2];
__device__ float2 g_nwim[HH*NN/2];
__device__ float2 g_cre [HH*NN/2];
__device__ float2 g_cim [HH*NN/2];
__device__ float  g_wTre[HH*NN];
__device__ float  g_wTim[HH*NN];
__device__ float  g_stre[NSEQ*NCHK*NN];
__device__ float  g_stim[NSEQ*NCHK*NN];
__device__ float  g_gb  [BB*2*HH];
__device__ float  g_part[HH*BB*2];
__device__ float  g_mean[HH];
__device__ float  g_rstd[HH];

__device__ __forceinline__ u64 pk2(float lo, float hi) {
    u64 r; asm("mov.b64 %0, {%1, %2};" : "=l"(r) : "f"(lo), "f"(hi)); return r;
}
__device__ __forceinline__ void upk2(u64 v, float& lo, float& hi) {
    asm("mov.b64 {%0, %1}, %2;" : "=f"(lo), "=f"(hi) : "l"(v));
}
__device__ __forceinline__ u64 ffma2(u64 a, u64 b, u64 c) {
    u64 d; asm("fma.rn.f32x2 %0, %1, %2, %3;" : "=l"(d) : "l"(a), "l"(b), "l"(c)); return d;
}
__device__ __forceinline__ u64 fmul2(u64 a, u64 b) {
    u64 d; asm("mul.rn.f32x2 %0, %1, %2;" : "=l"(d) : "l"(a), "l"(b)); return d;
}

/* ---------------- prep: S4D derived params + FiLM GEMM ---------------- */
__global__ void prep_kernel(const float* __restrict__ log_dt, const float* __restrict__ log_A_real,
                            const float* __restrict__ A_imag, const float* __restrict__ C_re,
                            const float* __restrict__ C_im,  const float* __restrict__ cond,
                            const float* __restrict__ film_w, const float* __restrict__ film_b)
{
    int id = blockIdx.x*128 + threadIdx.x;
    if (id < HH*NN) {
        int h = id >> 5;
        double dt  = exp((double)log_dt[h]);
        double Are = -exp((double)log_A_real[id]);
        double Aim = (double)A_imag[id];
        double dre = Are*dt, dim = Aim*dt;
        double er  = exp(dre);
        double wre = er*cos(dim), wim = er*sin(dim);
        double e1r = wre - 1.0,   e1i = wim;
        double Cr = (double)C_re[id], Ci = (double)C_im[id];
        double numr = Cr*e1r - Ci*e1i;
        double numi = Cr*e1i + Ci*e1r;
        double den  = Are*Are + Aim*Aim;
        ((float*)g_wre )[id] = (float)wre;
        ((float*)g_wim )[id] = (float)wim;
        ((float*)g_nwim)[id] = (float)(-wim);
        ((float*)g_cre )[id] = (float)((numr*Are + numi*Aim)/den);
        ((float*)g_cim )[id] = (float)((numi*Are - numr*Aim)/den);
        double tr = dre*(double)TT, ti = dim*(double)TT;
        double et = exp(tr);
        g_wTre[id] = (float)(et*cos(ti));
        g_wTim[id] = (float)(et*sin(ti));
    } else if (id < HH*NN + BB*2*HH) {
        int j = id - HH*NN;
        int b = j >> 7, c = j & 127;
        double acc = (double)film_b[c];
        for (int d = 0; d < DCC; ++d)
            acc += (double)cond[b*DCC + d] * (double)film_w[c*DCC + d];
        g_gb[j] = (float)acc;
    }
}

/* ---------------- packed f32x2 64x64 channel GEMM ---------------- */
template<int MODE>
__global__ void __launch_bounds__(256) gemm64p_kernel(const float* __restrict__ xin,
        const float* __restrict__ W, const float* __restrict__ bias, const float* __restrict__ pa)
{
    __shared__ u64 wp[HH*HH];
    int tid = threadIdx.x;
    for (int i = tid; i < HH*HH; i += 256) {
        int g = i >> 6, h = i & 63;
        float w = W[i];
        wp[h*HH + g] = pk2(w, w);
    }
    __syncthreads();

    const float* src = (MODE == 0) ? xin : g_buf1;
    int half  = tid >> 7;
    int tl    = tid & 127;
    int gbase = half * 32;
    int b     = blockIdx.y;
    int p2    = blockIdx.x*256 + tl*2;
    size_t sb = (size_t)b*HH*LL + p2;

    u64 acc[32];
    #pragma unroll
    for (int g = 0; g < 32; ++g) { float bv = bias[gbase+g]; acc[g] = pk2(bv, bv); }

    #pragma unroll 2
    for (int h = 0; h < HH; ++h) {
        float2 xv = *reinterpret_cast<const float2*>(&src[sb + (size_t)h*LL]);
        u64 xp = pk2(xv.x, xv.y);
        const ulonglong2* wrow = reinterpret_cast<const ulonglong2*>(&wp[h*HH + gbase]);
        #pragma unroll
        for (int q = 0; q < 16; ++q) {
            ulonglong2 w2 = wrow[q];
            acc[2*q  ] = ffma2(w2.x, xp, acc[2*q  ]);
            acc[2*q+1] = ffma2(w2.y, xp, acc[2*q+1]);
        }
    }
    float aa = (MODE == 0) ? pa[0] : 0.f;
    #pragma unroll
    for (int g = 0; g < 32; ++g) {
        float lo, hi; upk2(acc[g], lo, hi);
        if (MODE == 0) {
            lo = (lo >= 0.f) ? lo : aa*lo;
            hi = (hi >= 0.f) ? hi : aa*hi;
        }
        float2 o; o.x = lo; o.y = hi;
        *reinterpret_cast<float2*>(&g_buf0[(size_t)b*HH*LL + (size_t)(gbase+g)*LL + p2]) = o;
    }
}

/* ---------------- scanA: chunk-local end-states + fused inter-chunk prefix ---------------- */
__global__ void __launch_bounds__(256, 4) scanA_kernel()
{
    __shared__ float sh[64*33];
    __shared__ float st_re[2][NCHK][NN];
    __shared__ float st_im[2][NCHK][NN];
    int tid  = threadIdx.x;
    int ul   = tid >> 2, q = tid & 3;
    int u    = blockIdx.x*64 + ul;
    int bh   = u >> 5;
    int hch  = bh & 63;
    int pb   = hch*16 + q*4;

    const u64* wrp  = (const u64*)g_wre  + pb;
    const u64* wip  = (const u64*)g_wim  + pb;
    const u64* nwip = (const u64*)g_nwim + pb;
    u64 wre[4], wim[4], nwim[4], sre[4], sim[4];
    #pragma unroll
    for (int k = 0; k < 4; ++k) {
        wre[k] = wrp[k]; wim[k] = wip[k]; nwim[k] = nwip[k];
        sre[k] = 0ULL; sim[k] = 0ULL;
    }
    size_t gbase = (size_t)blockIdx.x * 64 * TT;

    for (int tile = 0; tile < TT/32; ++tile) {
        __syncthreads();
        #pragma unroll
        for (int it = 0; it < 8; ++it) {
            int idx = it*256 + tid;
            int uu = idx >> 5, lo = idx & 31;
            sh[uu*33 + lo] = g_buf0[gbase + (size_t)uu*TT + tile*32 + lo];
        }
        __syncthreads();
        #pragma unroll 4
        for (int l = 0; l < 32; ++l) {
            float hv = sh[ul*33 + l];
            u64 hh = pk2(hv, hv);
            #pragma unroll
            for (int k = 0; k < 4; ++k) {
                u64 t  = ffma2(nwim[k], sim[k], hh);
                u64 t2 = fmul2(wim[k],  sre[k]);
                sre[k] = ffma2(wre[k], sre[k], t);
                sim[k] = ffma2(wre[k], sim[k], t2);
            }
        }
    }
    int bh_loc = ul >> 5, c = ul & 31;
    #pragma unroll
    for (int k = 0; k < 4; ++k) {
        float a, bq;
        int n0 = q*8 + k*2;
        upk2(sre[k], a, bq); st_re[bh_loc][c][n0] = a; st_re[bh_loc][c][n0+1] = bq;
        upk2(sim[k], a, bq); st_im[bh_loc][c][n0] = a; st_im[bh_loc][c][n0+1] = bq;
    }
    __syncthreads();
    if (tid < 64) {
        int bl = tid >> 5, n = tid & 31;
        int hc = (blockIdx.x*2 + bl) & 63;
        float wtr = g_wTre[hc*NN + n], wti = g_wTim[hc*NN + n];
        float Sre = 0.f, Sim = 0.f;
        #pragma unroll
        for (int cc = 0; cc < NCHK; ++cc) {
            float lre = st_re[bl][cc][n], lim = st_im[bl][cc][n];
            st_re[bl][cc][n] = Sre; st_im[bl][cc][n] = Sim;
            float nr = fmaf(wtr, Sre, fmaf(-wti, Sim, lre));
            float ni = fmaf(wtr, Sim, fmaf( wti, Sre, lim));
            Sre = nr; Sim = ni;
        }
    }
    __syncthreads();
    const float* fre = &st_re[0][0][0];
    const float* fim = &st_im[0][0][0];
    size_t ob = (size_t)blockIdx.x * 2048;
    for (int i = tid; i < 2048; i += 256) {
        g_stre[ob + i] = fre[i];
        g_stim[ob + i] = fim[i];
    }
}

/* ---------------- scanC: full scan + output; 2 threads/unit, light MIO ----------------
   Each thread owns 16 complex states (8 f32x2 pairs). Per l-step: 24 f32x2 fma,
   one LDS (h value) and one STS (scalar partial). Pairwise reduce after the tile. */
__global__ void __launch_bounds__(128, 3) scanC_kernel(const float* __restrict__ Dskip)
{
    __shared__ float sh [64*33];
    __shared__ float sho[64*33];
    __shared__ float sp [32*128];
    int tid  = threadIdx.x;
    int ul   = tid >> 1, q = tid & 1;
    int u    = blockIdx.x*64 + ul;
    int bh   = u >> 5, c = u & 31;
    int hch  = bh & 63;
    int pb   = hch*16 + q*8;

    const u64* wrp  = (const u64*)g_wre  + pb;
    const u64* wip  = (const u64*)g_wim  + pb;
    const u64* nwip = (const u64*)g_nwim + pb;
    const u64* crp  = (const u64*)g_cre  + pb;
    const float2* cif = (const float2*)g_cim + pb;
    u64 wre[8], wim[8], nwim[8], cre[8], ncim[8], sre[8], sim[8];
    int sb = (bh*NCHK + c)*NN + q*16;
    const u64* ire = (const u64*)(g_stre + sb);
    const u64* iim = (const u64*)(g_stim + sb);
    #pragma unroll
    for (int k = 0; k < 8; ++k) {
        wre[k] = wrp[k]; wim[k] = wip[k]; nwim[k] = nwip[k];
        cre[k] = crp[k];
        float2 cv = cif[k];
        ncim[k] = pk2(-cv.x, -cv.y);
        sre[k] = ire[k]; sim[k] = iim[k];
    }
    float dsk0 = Dskip[(blockIdx.x*2    ) & 63];
    float dsk1 = Dskip[(blockIdx.x*2 + 1) & 63];
    size_t gbase = (size_t)blockIdx.x * 64 * TT;

    for (int tile = 0; tile < TT/32; ++tile) {
        __syncthreads();
        #pragma unroll
        for (int it = 0; it < 16; ++it) {
            int idx = it*128 + tid;
            int uu = idx >> 5, lo = idx & 31;
            sh[uu*33 + lo] = g_buf0[gbase + (size_t)uu*TT + tile*32 + lo];
        }
        __syncthreads();
        #pragma unroll 2
        for (int l = 0; l < 32; ++l) {
            float hv = sh[ul*33 + l];
            u64 hh = pk2(hv, hv);
            u64 acc = 0ULL;
            #pragma unroll
            for (int k = 0; k < 8; ++k) {
                u64 t  = ffma2(nwim[k], sim[k], hh);
                u64 t2 = fmul2(wim[k],  sre[k]);
                sre[k] = ffma2(wre[k], sre[k], t);
                sim[k] = ffma2(wre[k], sim[k], t2);
                acc = ffma2(cre[k],  sre[k], acc);
                acc = ffma2(ncim[k], sim[k], acc);
            }
            float a0, a1; upk2(acc, a0, a1);
            sp[l*128 + tid] = a0 + a1;
        }
        __syncthreads();
        /* reduce 2 partials per output */
        #pragma unroll
        for (int it = 0; it < 16; ++it) {
            int idx = it*128 + tid;
            int uu = idx & 63, lo = idx >> 6;
            float2 v = *reinterpret_cast<const float2*>(&sp[lo*128 + uu*2]);
            float hv = sh[uu*33 + lo];
            float dsk = (uu < 32) ? dsk0 : dsk1;
            sho[uu*33 + lo] = fmaf(dsk, hv, 2.f*(v.x + v.y));
        }
        __syncthreads();
        #pragma unroll
        for (int it = 0; it < 16; ++it) {
            int idx = it*128 + tid;
            int uu = idx >> 5, lo = idx & 31;
            g_buf1[gbase + (size_t)uu*TT + tile*32 + lo] = sho[uu*33 + lo];
        }
    }
}

/* ---------------- BN statistics (deterministic two-stage) ---------------- */
__global__ void __launch_bounds__(256) stats_kernel()
{
    int b = blockIdx.x, g = blockIdx.y;
    const float4* p = (const float4*)(g_buf0 + ((size_t)b*HH + g)*LL);
    float s = 0.f, s2 = 0.f;
    for (int i = threadIdx.x; i < LL/4; i += 256) {
        float4 v = p[i];
        s  += v.x + v.y + v.z + v.w;
        s2 += v.x*v.x + v.y*v.y + v.z*v.z + v.w*v.w;
    }
    __shared__ float r1[256], r2[256];
    r1[threadIdx.x] = s; r2[threadIdx.x] = s2;
    __syncthreads();
    for (int o = 128; o > 0; o >>= 1) {
        if (threadIdx.x < o) { r1[threadIdx.x] += r1[threadIdx.x+o]; r2[threadIdx.x] += r2[threadIdx.x+o]; }
        __syncthreads();
    }
    if (threadIdx.x == 0) {
        g_part[(g*BB + b)*2    ] = r1[0];
        g_part[(g*BB + b)*2 + 1] = r2[0];
    }
}

__global__ void fin_kernel()
{
    int g = threadIdx.x;
    if (g >= HH) return;
    float s = 0.f, s2 = 0.f;
    for (int b = 0; b < BB; ++b) { s += g_part[(g*BB+b)*2]; s2 += g_part[(g*BB+b)*2 + 1]; }
    float inv = 1.f / (float)(BB*LL);
    float m   = s * inv;
    float var = fmaf(s2, inv, -m*m);
    g_mean[g] = m;
    g_rstd[g] = rsqrtf(var + 1e-5f);
}

/* ---------------- fused BN + FiLM + PReLU + residual ---------------- */
__global__ void __launch_bounds__(256) final_kernel(const float* __restrict__ x,
        const float* __restrict__ res_w, const float* __restrict__ pa2, float* __restrict__ out)
{
    int idx = blockIdx.x*256 + threadIdx.x;
    int row = idx >> 12;
    int b = row >> 6, g = row & 63;
    float m  = g_mean[g], r = g_rstd[g];
    float ga = g_gb[b*2*HH + g], be = g_gb[b*2*HH + HH + g];
    float rw = res_w[g], aa = pa2[0];
    float4 y  = ((const float4*)g_buf0)[idx];
    float4 xv = ((const float4*)x)[idx];
    float4 o; float v;
    v = (y.x - m)*r; v = fmaf(ga, v, be); v = (v >= 0.f) ? v : aa*v; o.x = fmaf(rw, xv.x, v);
    v = (y.y - m)*r; v = fmaf(ga, v, be); v = (v >= 0.f) ? v : aa*v; o.y = fmaf(rw, xv.y, v);
    v = (y.z - m)*r; v = fmaf(ga, v, be); v = (v >= 0.f) ? v : aa*v; o.z = fmaf(rw, xv.z, v);
    v = (y.w - m)*r; v = fmaf(ga, v, be); v = (v >= 0.f) ? v : aa*v; o.w = fmaf(rw, xv.w, v);
    ((float4*)out)[idx] = o;
}

extern "C" void kernel_launch(void* const* d_in, const int* in_sizes, int n_in,
                              void* d_out, int out_size)
{
    const float* x        = (const float*)d_in[0];
    const float* cond     = (const float*)d_in[1];
    const float* linear_w = (const float*)d_in[2];
    const float* linear_b = (const float*)d_in[3];
    const float* prelu1_a = (const float*)d_in[4];
    const float* log_dt   = (const float*)d_in[5];
    const float* log_A_r  = (const float*)d_in[6];
    const float* A_imag   = (const float*)d_in[7];
    const float* C_re     = (const float*)d_in[8];
    const float* C_im     = (const float*)d_in[9];
    const float* Dskip    = (const float*)d_in[10];
    const float* out_w    = (const float*)d_in[11];
    const float* out_b    = (const float*)d_in[12];
    const float* film_w   = (const float*)d_in[13];
    const float* film_b   = (const float*)d_in[14];
    const float* prelu2_a = (const float*)d_in[15];
    const float* res_w    = (const float*)d_in[16];
    float* out = (float*)d_out;

    prep_kernel<<<32, 128>>>(log_dt, log_A_r, A_imag, C_re, C_im, cond, film_w, film_b);
    gemm64p_kernel<0><<<dim3(LL/256, BB), 256>>>(x, linear_w, linear_b, prelu1_a);
    scanA_kernel<<<NSEQ*NCHK/64, 256>>>();
    scanC_kernel<<<NSEQ*NCHK/64, 128>>>(Dskip);
    gemm64p_kernel<1><<<dim3(LL/256, BB), 256>>>(x, out_w, out_b, prelu1_a);
    stats_kernel<<<dim3(BB, HH), 256>>>();
    fin_kernel<<<1, 64>>>();
    final_kernel<<<NTOT/4/256, 256>>>(x, res_w, prelu2_a, out);
}

// round 14
// speedup vs baseline: 1.0972x; 1.0972x over previous
#include <cuda_runtime.h>
#include <cstdint>

#define BB   16
#define HH   64
#define LL   16384
#define NN   32
#define DCC  128
#define TT   512
#define NCHK 32
#define NSEQ (BB*HH)
#define NTOT (BB*HH*LL)
#define SROW 36            /* smem tile row stride (16B-aligned for cp.async) */

typedef unsigned long long u64;

__device__ float  g_buf0[NTOT];
__device__ float  g_buf1[NTOT];
__device__ float2 g_wre [HH*NN/2];
__device__ float2 g_wim [HH*NN/2];
__device__ float2 g_nwim[HH*NN/2];
__device__ float2 g_cre [HH*NN/2];
__device__ float2 g_cim [HH*NN/2];
__device__ float  g_wTre[HH*NN];
__device__ float  g_wTim[HH*NN];
__device__ float  g_stre[NSEQ*NCHK*NN];
__device__ float  g_stim[NSEQ*NCHK*NN];
__device__ float  g_gb  [BB*2*HH];
__device__ float  g_part[HH*BB*2];
__device__ float  g_mean[HH];
__device__ float  g_rstd[HH];

__device__ __forceinline__ u64 pk2(float lo, float hi) {
    u64 r; asm("mov.b64 %0, {%1, %2};" : "=l"(r) : "f"(lo), "f"(hi)); return r;
}
__device__ __forceinline__ void upk2(u64 v, float& lo, float& hi) {
    asm("mov.b64 {%0, %1}, %2;" : "=f"(lo), "=f"(hi) : "l"(v));
}
__device__ __forceinline__ u64 ffma2(u64 a, u64 b, u64 c) {
    u64 d; asm("fma.rn.f32x2 %0, %1, %2, %3;" : "=l"(d) : "l"(a), "l"(b), "l"(c)); return d;
}
__device__ __forceinline__ u64 fmul2(u64 a, u64 b) {
    u64 d; asm("mul.rn.f32x2 %0, %1, %2;" : "=l"(d) : "l"(a), "l"(b)); return d;
}
__device__ __forceinline__ void cpa16(const void* smem_dst, const void* gsrc) {
    unsigned saddr = (unsigned)__cvta_generic_to_shared(smem_dst);
    asm volatile("cp.async.cg.shared.global [%0], [%1], 16;" :: "r"(saddr), "l"(gsrc));
}
__device__ __forceinline__ void cpa_commit() { asm volatile("cp.async.commit_group;"); }
__device__ __forceinline__ void cpa_wait1()  { asm volatile("cp.async.wait_group 1;"); }
__device__ __forceinline__ void cpa_wait0()  { asm volatile("cp.async.wait_group 0;"); }

/* ---------------- prep: S4D derived params + FiLM GEMM ---------------- */
__global__ void prep_kernel(const float* __restrict__ log_dt, const float* __restrict__ log_A_real,
                            const float* __restrict__ A_imag, const float* __restrict__ C_re,
                            const float* __restrict__ C_im,  const float* __restrict__ cond,
                            const float* __restrict__ film_w, const float* __restrict__ film_b)
{
    int id = blockIdx.x*128 + threadIdx.x;
    if (id < HH*NN) {
        int h = id >> 5;
        double dt  = exp((double)log_dt[h]);
        double Are = -exp((double)log_A_real[id]);
        double Aim = (double)A_imag[id];
        double dre = Are*dt, dim = Aim*dt;
        double er  = exp(dre);
        double wre = er*cos(dim), wim = er*sin(dim);
        double e1r = wre - 1.0,   e1i = wim;
        double Cr = (double)C_re[id], Ci = (double)C_im[id];
        double numr = Cr*e1r - Ci*e1i;
        double numi = Cr*e1i + Ci*e1r;
        double den  = Are*Are + Aim*Aim;
        ((float*)g_wre )[id] = (float)wre;
        ((float*)g_wim )[id] = (float)wim;
        ((float*)g_nwim)[id] = (float)(-wim);
        ((float*)g_cre )[id] = (float)((numr*Are + numi*Aim)/den);
        ((float*)g_cim )[id] = (float)((numi*Are - numr*Aim)/den);
        double tr = dre*(double)TT, ti = dim*(double)TT;
        double et = exp(tr);
        g_wTre[id] = (float)(et*cos(ti));
        g_wTim[id] = (float)(et*sin(ti));
    } else if (id < HH*NN + BB*2*HH) {
        int j = id - HH*NN;
        int b = j >> 7, c = j & 127;
        double acc = (double)film_b[c];
        for (int d = 0; d < DCC; ++d)
            acc += (double)cond[b*DCC + d] * (double)film_w[c*DCC + d];
        g_gb[j] = (float)acc;
    }
}

/* ---------------- packed f32x2 64x64 channel GEMM ---------------- */
template<int MODE>
__global__ void __launch_bounds__(256) gemm64p_kernel(const float* __restrict__ xin,
        const float* __restrict__ W, const float* __restrict__ bias, const float* __restrict__ pa)
{
    __shared__ u64 wp[HH*HH];
    int tid = threadIdx.x;
    for (int i = tid; i < HH*HH; i += 256) {
        int g = i >> 6, h = i & 63;
        float w = W[i];
        wp[h*HH + g] = pk2(w, w);
    }
    __syncthreads();

    const float* src = (MODE == 0) ? xin : g_buf1;
    int half  = tid >> 7;
    int tl    = tid & 127;
    int gbase = half * 32;
    int b     = blockIdx.y;
    int p2    = blockIdx.x*256 + tl*2;
    size_t sb = (size_t)b*HH*LL + p2;

    u64 acc[32];
    #pragma unroll
    for (int g = 0; g < 32; ++g) { float bv = bias[gbase+g]; acc[g] = pk2(bv, bv); }

    #pragma unroll 2
    for (int h = 0; h < HH; ++h) {
        float2 xv = *reinterpret_cast<const float2*>(&src[sb + (size_t)h*LL]);
        u64 xp = pk2(xv.x, xv.y);
        const ulonglong2* wrow = reinterpret_cast<const ulonglong2*>(&wp[h*HH + gbase]);
        #pragma unroll
        for (int q = 0; q < 16; ++q) {
            ulonglong2 w2 = wrow[q];
            acc[2*q  ] = ffma2(w2.x, xp, acc[2*q  ]);
            acc[2*q+1] = ffma2(w2.y, xp, acc[2*q+1]);
        }
    }
    float aa = (MODE == 0) ? pa[0] : 0.f;
    #pragma unroll
    for (int g = 0; g < 32; ++g) {
        float lo, hi; upk2(acc[g], lo, hi);
        if (MODE == 0) {
            lo = (lo >= 0.f) ? lo : aa*lo;
            hi = (hi >= 0.f) ? hi : aa*hi;
        }
        float2 o; o.x = lo; o.y = hi;
        *reinterpret_cast<float2*>(&g_buf0[(size_t)b*HH*LL + (size_t)(gbase+g)*LL + p2]) = o;
    }
}

/* ---------------- scanA: cp.async double-buffered; 4 thr/unit ---------------- */
__global__ void __launch_bounds__(256, 4) scanA_kernel()
{
    __shared__ float sh[2][64*SROW];
    __shared__ float st_re[2][NCHK][NN];
    __shared__ float st_im[2][NCHK][NN];
    int tid  = threadIdx.x;
    int ul   = tid >> 2, q = tid & 3;
    int u    = blockIdx.x*64 + ul;
    int bh   = u >> 5;
    int hch  = bh & 63;
    int pb   = hch*16 + q*4;

    const u64* wrp  = (const u64*)g_wre  + pb;
    const u64* wip  = (const u64*)g_wim  + pb;
    const u64* nwip = (const u64*)g_nwim + pb;
    u64 wre[4], wim[4], nwim[4], sre[4], sim[4];
    #pragma unroll
    for (int k = 0; k < 4; ++k) {
        wre[k] = wrp[k]; wim[k] = wip[k]; nwim[k] = nwip[k];
        sre[k] = 0ULL; sim[k] = 0ULL;
    }
    size_t gbase = (size_t)blockIdx.x * 64 * TT;

    /* stage tile 0 */
    #pragma unroll
    for (int i = 0; i < 2; ++i) {
        int cid = i*256 + tid;
        int uu = cid >> 3, c8 = cid & 7;
        cpa16(&sh[0][uu*SROW + c8*4], &g_buf0[gbase + (size_t)uu*TT + c8*4]);
    }
    cpa_commit();

    for (int tile = 0; tile < TT/32; ++tile) {
        if (tile + 1 < TT/32) {
            float* dst = sh[(tile+1) & 1];
            #pragma unroll
            for (int i = 0; i < 2; ++i) {
                int cid = i*256 + tid;
                int uu = cid >> 3, c8 = cid & 7;
                cpa16(&dst[uu*SROW + c8*4], &g_buf0[gbase + (size_t)uu*TT + (tile+1)*32 + c8*4]);
            }
            cpa_commit();
            cpa_wait1();
        } else {
            cpa_wait0();
        }
        __syncthreads();
        const float* cur = sh[tile & 1];
        #pragma unroll 4
        for (int l = 0; l < 32; ++l) {
            float hv = cur[ul*SROW + l];
            u64 hh = pk2(hv, hv);
            #pragma unroll
            for (int k = 0; k < 4; ++k) {
                u64 t  = ffma2(nwim[k], sim[k], hh);
                u64 t2 = fmul2(wim[k],  sre[k]);
                sre[k] = ffma2(wre[k], sre[k], t);
                sim[k] = ffma2(wre[k], sim[k], t2);
            }
        }
        __syncthreads();   /* buffer reuse safety */
    }
    int bh_loc = ul >> 5, c = ul & 31;
    #pragma unroll
    for (int k = 0; k < 4; ++k) {
        float a, bq;
        int n0 = q*8 + k*2;
        upk2(sre[k], a, bq); st_re[bh_loc][c][n0] = a; st_re[bh_loc][c][n0+1] = bq;
        upk2(sim[k], a, bq); st_im[bh_loc][c][n0] = a; st_im[bh_loc][c][n0+1] = bq;
    }
    __syncthreads();
    if (tid < 64) {
        int bl = tid >> 5, n = tid & 31;
        int hc = (blockIdx.x*2 + bl) & 63;
        float wtr = g_wTre[hc*NN + n], wti = g_wTim[hc*NN + n];
        float Sre = 0.f, Sim = 0.f;
        #pragma unroll
        for (int cc = 0; cc < NCHK; ++cc) {
            float lre = st_re[bl][cc][n], lim = st_im[bl][cc][n];
            st_re[bl][cc][n] = Sre; st_im[bl][cc][n] = Sim;
            float nr = fmaf(wtr, Sre, fmaf(-wti, Sim, lre));
            float ni = fmaf(wtr, Sim, fmaf( wti, Sre, lim));
            Sre = nr; Sim = ni;
        }
    }
    __syncthreads();
    const float* fre = &st_re[0][0][0];
    const float* fim = &st_im[0][0][0];
    size_t ob = (size_t)blockIdx.x * 2048;
    for (int i = tid; i < 2048; i += 256) {
        g_stre[ob + i] = fre[i];
        g_stim[ob + i] = fim[i];
    }
}

/* ---------------- scanC: cp.async double-buffered; 4 thr/unit + STS partials ---------------- */
__global__ void __launch_bounds__(256, 3) scanC_kernel(const float* __restrict__ Dskip)
{
    __shared__ float sh [2][64*SROW];
    __shared__ float sho[64*33];
    __shared__ float sp [32*256];
    int tid  = threadIdx.x;
    int ul   = tid >> 2, q = tid & 3;
    int u    = blockIdx.x*64 + ul;
    int bh   = u >> 5, c = u & 31;
    int hch  = bh & 63;
    int pb   = hch*16 + q*4;

    const u64* wrp  = (const u64*)g_wre  + pb;
    const u64* wip  = (const u64*)g_wim  + pb;
    const u64* nwip = (const u64*)g_nwim + pb;
    const u64* crp  = (const u64*)g_cre  + pb;
    const float2* cif = (const float2*)g_cim + pb;
    u64 wre[4], wim[4], nwim[4], cre[4], ncim[4], sre[4], sim[4];
    int sb = (bh*NCHK + c)*NN + q*8;
    const u64* ire = (const u64*)(g_stre + sb);
    const u64* iim = (const u64*)(g_stim + sb);
    #pragma unroll
    for (int k = 0; k < 4; ++k) {
        wre[k] = wrp[k]; wim[k] = wip[k]; nwim[k] = nwip[k];
        cre[k] = crp[k];
        float2 cv = cif[k];
        ncim[k] = pk2(-cv.x, -cv.y);
        sre[k] = ire[k]; sim[k] = iim[k];
    }
    float dsk0 = Dskip[(blockIdx.x*2    ) & 63];
    float dsk1 = Dskip[(blockIdx.x*2 + 1) & 63];
    size_t gbase = (size_t)blockIdx.x * 64 * TT;

    /* stage tile 0 */
    #pragma unroll
    for (int i = 0; i < 2; ++i) {
        int cid = i*256 + tid;
        int uu = cid >> 3, c8 = cid & 7;
        cpa16(&sh[0][uu*SROW + c8*4], &g_buf0[gbase + (size_t)uu*TT + c8*4]);
    }
    cpa_commit();

    for (int tile = 0; tile < TT/32; ++tile) {
        if (tile + 1 < TT/32) {
            float* dst = sh[(tile+1) & 1];
            #pragma unroll
            for (int i = 0; i < 2; ++i) {
                int cid = i*256 + tid;
                int uu = cid >> 3, c8 = cid & 7;
                cpa16(&dst[uu*SROW + c8*4], &g_buf0[gbase + (size_t)uu*TT + (tile+1)*32 + c8*4]);
            }
            cpa_commit();
            cpa_wait1();
        } else {
            cpa_wait0();
        }
        __syncthreads();
        const float* cur = sh[tile & 1];
        #pragma unroll 4
        for (int l = 0; l < 32; ++l) {
            float hv = cur[ul*SROW + l];
            u64 hh = pk2(hv, hv);
            u64 acc = 0ULL;
            #pragma unroll
            for (int k = 0; k < 4; ++k) {
                u64 t  = ffma2(nwim[k], sim[k], hh);
                u64 t2 = fmul2(wim[k],  sre[k]);
                sre[k] = ffma2(wre[k], sre[k], t);
                sim[k] = ffma2(wre[k], sim[k], t2);
                acc = ffma2(cre[k],  sre[k], acc);
                acc = ffma2(ncim[k], sim[k], acc);
            }
            float a0, a1; upk2(acc, a0, a1);
            sp[l*256 + tid] = a0 + a1;
        }
        __syncthreads();
        /* reduce 4 partials per output */
        #pragma unroll
        for (int it = 0; it < 8; ++it) {
            int idx = it*256 + tid;
            int uu = idx & 63, lo = idx >> 6;
            float4 v = *reinterpret_cast<const float4*>(&sp[lo*256 + uu*4]);
            float hv = cur[uu*SROW + lo];
            float dsk = (uu < 32) ? dsk0 : dsk1;
            float p = (v.x + v.y) + (v.z + v.w);
            sho[uu*33 + lo] = fmaf(dsk, hv, 2.f*p);
        }
        __syncthreads();
        #pragma unroll
        for (int it = 0; it < 8; ++it) {
            int idx = it*256 + tid;
            int uu = idx >> 5, lo = idx & 31;
            g_buf1[gbase + (size_t)uu*TT + tile*32 + lo] = sho[uu*33 + lo];
        }
    }
}

/* ---------------- BN statistics (deterministic two-stage) ---------------- */
__global__ void __launch_bounds__(256) stats_kernel()
{
    int b = blockIdx.x, g = blockIdx.y;
    const float4* p = (const float4*)(g_buf0 + ((size_t)b*HH + g)*LL);
    float s = 0.f, s2 = 0.f;
    for (int i = threadIdx.x; i < LL/4; i += 256) {
        float4 v = p[i];
        s  += v.x + v.y + v.z + v.w;
        s2 += v.x*v.x + v.y*v.y + v.z*v.z + v.w*v.w;
    }
    __shared__ float r1[256], r2[256];
    r1[threadIdx.x] = s; r2[threadIdx.x] = s2;
    __syncthreads();
    for (int o = 128; o > 0; o >>= 1) {
        if (threadIdx.x < o) { r1[threadIdx.x] += r1[threadIdx.x+o]; r2[threadIdx.x] += r2[threadIdx.x+o]; }
        __syncthreads();
    }
    if (threadIdx.x == 0) {
        g_part[(g*BB + b)*2    ] = r1[0];
        g_part[(g*BB + b)*2 + 1] = r2[0];
    }
}

__global__ void fin_kernel()
{
    int g = threadIdx.x;
    if (g >= HH) return;
    float s = 0.f, s2 = 0.f;
    for (int b = 0; b < BB; ++b) { s += g_part[(g*BB+b)*2]; s2 += g_part[(g*BB+b)*2 + 1]; }
    float inv = 1.f / (float)(BB*LL);
    float m   = s * inv;
    float var = fmaf(s2, inv, -m*m);
    g_mean[g] = m;
    g_rstd[g] = rsqrtf(var + 1e-5f);
}

/* ---------------- fused BN + FiLM + PReLU + residual ---------------- */
__global__ void __launch_bounds__(256) final_kernel(const float* __restrict__ x,
        const float* __restrict__ res_w, const float* __restrict__ pa2, float* __restrict__ out)
{
    int idx = blockIdx.x*256 + threadIdx.x;
    int row = idx >> 12;
    int b = row >> 6, g = row & 63;
    float m  = g_mean[g], r = g_rstd[g];
    float ga = g_gb[b*2*HH + g], be = g_gb[b*2*HH + HH + g];
    float rw = res_w[g], aa = pa2[0];
    float4 y  = ((const float4*)g_buf0)[idx];
    float4 xv = ((const float4*)x)[idx];
    float4 o; float v;
    v = (y.x - m)*r; v = fmaf(ga, v, be); v = (v >= 0.f) ? v : aa*v; o.x = fmaf(rw, xv.x, v);
    v = (y.y - m)*r; v = fmaf(ga, v, be); v = (v >= 0.f) ? v : aa*v; o.y = fmaf(rw, xv.y, v);
    v = (y.z - m)*r; v = fmaf(ga, v, be); v = (v >= 0.f) ? v : aa*v; o.z = fmaf(rw, xv.z, v);
    v = (y.w - m)*r; v = fmaf(ga, v, be); v = (v >= 0.f) ? v : aa*v; o.w = fmaf(rw, xv.w, v);
    ((float4*)out)[idx] = o;
}

extern "C" void kernel_launch(void* const* d_in, const int* in_sizes, int n_in,
                              void* d_out, int out_size)
{
    const float* x        = (const float*)d_in[0];
    const float* cond     = (const float*)d_in[1];
    const float* linear_w = (const float*)d_in[2];
    const float* linear_b = (const float*)d_in[3];
    const float* prelu1_a = (const float*)d_in[4];
    const float* log_dt   = (const float*)d_in[5];
    const float* log_A_r  = (const float*)d_in[6];
    const float* A_imag   = (const float*)d_in[7];
    const float* C_re     = (const float*)d_in[8];
    const float* C_im     = (const float*)d_in[9];
    const float* Dskip    = (const float*)d_in[10];
    const float* out_w    = (const float*)d_in[11];
    const float* out_b    = (const float*)d_in[12];
    const float* film_w   = (const float*)d_in[13];
    const float* film_b   = (const float*)d_in[14];
    const float* prelu2_a = (const float*)d_in[15];
    const float* res_w    = (const float*)d_in[16];
    float* out = (float*)d_out;

    prep_kernel<<<32, 128>>>(log_dt, log_A_r, A_imag, C_re, C_im, cond, film_w, film_b);
    gemm64p_kernel<0><<<dim3(LL/256, BB), 256>>>(x, linear_w, linear_b, prelu1_a);
    scanA_kernel<<<NSEQ*NCHK/64, 256>>>();
    scanC_kernel<<<NSEQ*NCHK/64, 256>>>(Dskip);
    gemm64p_kernel<1><<<dim3(LL/256, BB), 256>>>(x, out_w, out_b, prelu1_a);
    stats_kernel<<<dim3(BB, HH), 256>>>();
    fin_kernel<<<1, 64>>>();
    final_kernel<<<NTOT/4/256, 256>>>(x, res_w, prelu2_a, out);
}